// round 8
// baseline (speedup 1.0000x reference)
#include <cuda_runtime.h>
#include <cuda_fp16.h>
#include <math.h>
#include <stdint.h>

#define BB 8
#define TT 32
#define NN 1024
#define DIN 64
#define DR 128
#define DT_VAL 0.25f
#define KC 32
#define NCHUNK (NN / KC)
#define WSLOT (192 * 128)
#define AST 40      // A smem stride (halves)
#define BST 136     // B smem stride (halves)
#define GRIDN 128   // persistent grid size (<=148 SMs, all resident)

// ---------------- device scratch ----------------
__device__ float  g_h  [BB * NN * DR];
__device__ float  g_hv1[BB * NN * DR];
__device__ float  g_u  [BB * NN * DR];
__device__ float  g_z  [BB * NN * DR];
__device__ float  g_r  [BB * NN * DR];
__device__ float  g_obs[BB * TT];
__device__ __half g_Ah [BB * NN * NN];          // half A (16.7 MB)
__device__ __half g_Wh [6 * WSLOT];             // half weights
__device__ __half g_Woh[DR * DIN];              // half Wo
__device__ __half g_Pa [BB * NN * 256];         // ping
__device__ __half g_Pb [BB * NN * 256];         // pong
__device__ __half g_hv1h[(size_t)BB * TT * NN * DR]; // half hv1 history
__device__ unsigned g_barCount;

// ---------------- helpers ----------------
__device__ __forceinline__ void cpa16(void* s, const void* g) {
    uint32_t sa = (uint32_t)__cvta_generic_to_shared(s);
    asm volatile("cp.async.cg.shared.global [%0], [%1], 16;" :: "r"(sa), "l"(g));
}
__device__ __forceinline__ void ldsm4(uint32_t* r, uint32_t addr) {
    asm volatile("ldmatrix.sync.aligned.m8n8.x4.shared.b16 {%0,%1,%2,%3}, [%4];"
                 : "=r"(r[0]), "=r"(r[1]), "=r"(r[2]), "=r"(r[3]) : "r"(addr));
}
__device__ __forceinline__ void ldsm4t(uint32_t* r, uint32_t addr) {
    asm volatile("ldmatrix.sync.aligned.m8n8.x4.trans.shared.b16 {%0,%1,%2,%3}, [%4];"
                 : "=r"(r[0]), "=r"(r[1]), "=r"(r[2]), "=r"(r[3]) : "r"(addr));
}
#define MMA_F16(acc, a, b) \
    asm volatile( \
        "mma.sync.aligned.m16n8k16.row.col.f32.f16.f16.f32 " \
        "{%0,%1,%2,%3}, {%4,%5,%6,%7}, {%8,%9}, {%0,%1,%2,%3};" \
        : "+f"((acc)[0]), "+f"((acc)[1]), "+f"((acc)[2]), "+f"((acc)[3]) \
        : "r"((a)[0]), "r"((a)[1]), "r"((a)[2]), "r"((a)[3]), \
          "r"((b)[0]), "r"((b)[1]))

// ---------------- grid-wide barrier (monotonic count, no reset race) ------
__device__ __forceinline__ void grid_barrier(unsigned target128) {
    __threadfence();                 // every thread flushes its global writes
    __syncthreads();
    if (threadIdx.x == 0) {
        atomicAdd(&g_barCount, 1u);
        while (*(volatile unsigned*)&g_barCount < target128) { }
        __threadfence();
    }
    __syncthreads();
}

// ---------------- init h = broadcast(h0); reset barrier ----------------
__global__ void init_h_kernel(const float* __restrict__ h0) {
    if (blockIdx.x == 0 && threadIdx.x == 0) g_barCount = 0u;
    int idx = blockIdx.x * blockDim.x + threadIdx.x;
    const int total = BB * NN * DR;
    for (; idx < total; idx += gridDim.x * blockDim.x)
        g_h[idx] = h0[idx & (DR - 1)];
}

// ---------------- A -> half (vectorized) ----------------
__global__ void round_A_kernel(const float* __restrict__ A) {
    int idx = blockIdx.x * blockDim.x + threadIdx.x;
    const int total = BB * NN * NN / 4;
    for (; idx < total; idx += gridDim.x * blockDim.x) {
        float4 v = ((const float4*)A)[idx];
        union { uint2 u; __half2 h2[2]; } pk;
        pk.h2[0] = __floats2half2_rn(v.x, v.y);
        pk.h2[1] = __floats2half2_rn(v.z, v.w);
        *(uint2*)&g_Ah[idx * 4] = pk.u;
    }
}

// ---------------- weights -> half ----------------
__global__ void round_W_kernel(
    const float* __restrict__ W0, const float* __restrict__ W1,
    const float* __restrict__ Wout, const float* __restrict__ Wz,
    const float* __restrict__ Wr, const float* __restrict__ Wh,
    const float* __restrict__ Wo)
{
    const float* srcs[6] = {W0, W1, Wout, Wz, Wr, Wh};
    const int sizes[6] = {128*128, 128*128, 128*128, 192*128, 192*128, 192*128};
    for (int s = 0; s < 6; s++) {
        const float* src = srcs[s];
        __half* dst = g_Wh + s * WSLOT;
        for (int i = blockIdx.x * blockDim.x + threadIdx.x; i < sizes[s];
             i += gridDim.x * blockDim.x)
            dst[i] = __float2half(src[i]);
    }
    for (int i = blockIdx.x * blockDim.x + threadIdx.x; i < DR * DIN;
         i += gridDim.x * blockDim.x)
        g_Woh[i] = __float2half(Wo[i]);
}

// ---------------- obs[b,t] ----------------
__global__ void obs_kernel(const float* __restrict__ masks) {
    int bt = blockIdx.x;
    const float* m = masks + (size_t)bt * NN * DIN;
    float s = 0.f;
    for (int i = threadIdx.x; i < NN * DIN / 4; i += blockDim.x) {
        float4 v = ((const float4*)m)[i];
        s += fabsf(v.x) + fabsf(v.y) + fabsf(v.z) + fabsf(v.w);
    }
    __shared__ float red[256];
    red[threadIdx.x] = s;
    __syncthreads();
    for (int o = 128; o > 0; o >>= 1) {
        if (threadIdx.x < o) red[threadIdx.x] += red[threadIdx.x + o];
        __syncthreads();
    }
    if (threadIdx.x == 0) g_obs[bt] = (red[0] > 1e-4f) ? 1.f : 0.f;
}

// ---------------- projection stage (device fn; R6 proj_h body) ------------
// P[:, colOff:colOff+128] = half([x*m | h or r*h] @ W); 64 rows per CTA slab.
template<bool HAS_X, bool HAS_R>
__device__ __noinline__ void dev_proj(
    __half* smh, int b, int i0, int t,
    const float* xv, const float* xm,
    const float* h, const float* rr,
    const __half* W, __half* P, int ldP, int colOff, int Ktot)
{
    __syncthreads();    // global writes (u/r/hv1) by other warps visible
    __half* Xs = smh;
    __half* Ws = smh + 64 * AST;

    const int tid  = threadIdx.x;
    const int lane = tid & 31, warp = tid >> 5;
    const int wm = warp & 1, wn = warp >> 1;
    const int g  = lane >> 2, tig = lane & 3;
    const int quad = lane >> 3;
    const int lrow = (quad & 1) * 8 + (lane & 7);
    const int lcol = (quad >> 1) * 8;

    const int Kx = HAS_X ? DIN : 0;
    const float* hb  = h + ((size_t)b * NN + i0) * DR;
    const float* rb  = HAS_R ? rr + ((size_t)b * NN + i0) * DR : nullptr;
    const float* xvb = HAS_X ? xv + (((size_t)b * TT + t) * NN + i0) * DIN : nullptr;
    const float* xmb = HAS_X ? xm + (((size_t)b * TT + t) * NN + i0) * DIN : nullptr;

    const uint32_t sXs = (uint32_t)__cvta_generic_to_shared(Xs);
    const uint32_t sWs = (uint32_t)__cvta_generic_to_shared(Ws);

    float acc[2][4][4];
    #pragma unroll
    for (int mf = 0; mf < 2; mf++)
        #pragma unroll
        for (int nf = 0; nf < 4; nf++)
            #pragma unroll
            for (int e = 0; e < 4; e++) acc[mf][nf][e] = 0.f;

    for (int k0 = 0; k0 < Ktot; k0 += KC) {
        {
            int r = tid >> 2, kq = tid & 3;
            float va[8];
            if (HAS_X && k0 < DIN) {
                float4 v0 = *(const float4*)(xvb + (size_t)r * DIN + k0 + kq * 8);
                float4 v1 = *(const float4*)(xvb + (size_t)r * DIN + k0 + kq * 8 + 4);
                float4 m0 = *(const float4*)(xmb + (size_t)r * DIN + k0 + kq * 8);
                float4 m1 = *(const float4*)(xmb + (size_t)r * DIN + k0 + kq * 8 + 4);
                va[0]=v0.x*m0.x; va[1]=v0.y*m0.y; va[2]=v0.z*m0.z; va[3]=v0.w*m0.w;
                va[4]=v1.x*m1.x; va[5]=v1.y*m1.y; va[6]=v1.z*m1.z; va[7]=v1.w*m1.w;
            } else {
                int kh = k0 - Kx;
                float4 v0 = *(const float4*)(hb + (size_t)r * DR + kh + kq * 8);
                float4 v1 = *(const float4*)(hb + (size_t)r * DR + kh + kq * 8 + 4);
                va[0]=v0.x; va[1]=v0.y; va[2]=v0.z; va[3]=v0.w;
                va[4]=v1.x; va[5]=v1.y; va[6]=v1.z; va[7]=v1.w;
                if (HAS_R) {
                    float4 r0 = *(const float4*)(rb + (size_t)r * DR + kh + kq * 8);
                    float4 r1 = *(const float4*)(rb + (size_t)r * DR + kh + kq * 8 + 4);
                    va[0]*=r0.x; va[1]*=r0.y; va[2]*=r0.z; va[3]*=r0.w;
                    va[4]*=r1.x; va[5]*=r1.y; va[6]*=r1.z; va[7]*=r1.w;
                }
            }
            union { uint4 u; __half2 h2[4]; } pk;
            #pragma unroll
            for (int q = 0; q < 4; q++)
                pk.h2[q] = __floats2half2_rn(va[2*q], va[2*q+1]);
            *(uint4*)&Xs[r * AST + kq * 8] = pk.u;
        }
        #pragma unroll
        for (int l = 0; l < 2; l++) {
            int idx = tid + l * 256;
            int kk2 = idx >> 4, cq = idx & 15;
            *(uint4*)&Ws[kk2 * BST + cq * 8] =
                *(const uint4*)(W + (size_t)(k0 + kk2) * 128 + cq * 8);
        }
        __syncthreads();
        #pragma unroll
        for (int ks = 0; ks < 2; ks++) {
            const int kk = ks * 16;
            uint32_t a[2][4], bq[2][4];
            #pragma unroll
            for (int mf = 0; mf < 2; mf++)
                ldsm4(a[mf], sXs + ((wm*32 + mf*16 + lrow) * AST + kk + lcol) * 2);
            #pragma unroll
            for (int p = 0; p < 2; p++)
                ldsm4t(bq[p], sWs + ((kk + lrow) * BST + wn*32 + p*16 + lcol) * 2);
            #pragma unroll
            for (int mf = 0; mf < 2; mf++) {
                MMA_F16(acc[mf][0], a[mf], &bq[0][0]);
                MMA_F16(acc[mf][1], a[mf], &bq[0][2]);
                MMA_F16(acc[mf][2], a[mf], &bq[1][0]);
                MMA_F16(acc[mf][3], a[mf], &bq[1][2]);
            }
        }
        __syncthreads();
    }
    __half* Pb = P + ((size_t)b * NN + i0) * ldP + colOff;
    #pragma unroll
    for (int mf = 0; mf < 2; mf++)
        #pragma unroll
        for (int hf = 0; hf < 2; hf++) {
            int row = wm*32 + mf*16 + g + hf*8;
            #pragma unroll
            for (int nf = 0; nf < 4; nf++) {
                int col = wn*32 + nf*8 + 2*tig;
                *(__half2*)(Pb + (size_t)row * ldP + col) =
                    __floats2half2_rn(acc[mf][nf][hf*2 + 0], acc[mf][nf][hf*2 + 1]);
            }
        }
}

// ---------------- A-multiply stage (device fn; R6 amult_h body) ------------
// MODE: 0 u=tanh(G+b); 1 hv1=h+(G+b)*dt (+hist); 2 sig(G+b); 3 GRU blend.
template<int MODE>
__device__ __noinline__ void dev_amult(
    __half* smh, int b, int i0,
    const __half* Bop, int ldB, int colOff,
    const float* bias, float* dst,
    const float* hsrc, const float* zsrc, int tIdx, bool writeHist)
{
    __half* As = smh;
    __half* Bs = smh + 2 * 64 * AST;

    const int tid  = threadIdx.x;
    const int lane = tid & 31, warp = tid >> 5;
    const int wm = warp & 1, wn = warp >> 1;
    const int g  = lane >> 2, tig = lane & 3;
    const int quad = lane >> 3;
    const int lrow = (quad & 1) * 8 + (lane & 7);
    const int lcol = (quad >> 1) * 8;

    const __half* Ab = g_Ah + (size_t)b * NN * NN + (size_t)i0 * NN;
    const __half* Pb = Bop + (size_t)b * NN * ldB + colOff;

    const uint32_t sAs = (uint32_t)__cvta_generic_to_shared(As);
    const uint32_t sBs = (uint32_t)__cvta_generic_to_shared(Bs);

    float acc[2][4][4];
    #pragma unroll
    for (int mf = 0; mf < 2; mf++)
        #pragma unroll
        for (int nf = 0; nf < 4; nf++)
            #pragma unroll
            for (int e = 0; e < 4; e++) acc[mf][nf][e] = 0.f;

    auto prefetch = [&](int chunk, int buf) {
        __half* Ad = As + buf * 64 * AST;
        __half* Bd = Bs + buf * KC * BST;
        {
            int r = tid >> 2, kq = tid & 3;
            cpa16(Ad + r * AST + kq * 8, Ab + (size_t)r * NN + chunk * KC + kq * 8);
        }
        #pragma unroll
        for (int l = 0; l < 2; l++) {
            int idx = tid + l * 256;
            int kk2 = idx >> 4, cq = idx & 15;
            cpa16(Bd + kk2 * BST + cq * 8,
                  Pb + (size_t)(chunk * KC + kk2) * ldB + cq * 8);
        }
        asm volatile("cp.async.commit_group;");
    };

    prefetch(0, 0);
    for (int ch = 0; ch < NCHUNK; ch++) {
        int buf = ch & 1;
        if (ch + 1 < NCHUNK) {
            prefetch(ch + 1, buf ^ 1);
            asm volatile("cp.async.wait_group 1;");
        } else {
            asm volatile("cp.async.wait_group 0;");
        }
        __syncthreads();
        const uint32_t aBase = sAs + buf * 64 * AST * 2;
        const uint32_t bBase = sBs + buf * KC * BST * 2;
        #pragma unroll
        for (int ks = 0; ks < 2; ks++) {
            const int kk = ks * 16;
            uint32_t a[2][4], bq[2][4];
            #pragma unroll
            for (int mf = 0; mf < 2; mf++)
                ldsm4(a[mf], aBase + ((wm*32 + mf*16 + lrow) * AST + kk + lcol) * 2);
            #pragma unroll
            for (int p = 0; p < 2; p++)
                ldsm4t(bq[p], bBase + ((kk + lrow) * BST + wn*32 + p*16 + lcol) * 2);
            #pragma unroll
            for (int mf = 0; mf < 2; mf++) {
                MMA_F16(acc[mf][0], a[mf], &bq[0][0]);
                MMA_F16(acc[mf][1], a[mf], &bq[0][2]);
                MMA_F16(acc[mf][2], a[mf], &bq[1][0]);
                MMA_F16(acc[mf][3], a[mf], &bq[1][2]);
            }
        }
        __syncthreads();
    }

    const float ob = (MODE == 3) ? g_obs[b * TT + tIdx] : 0.f;
    #pragma unroll
    for (int mf = 0; mf < 2; mf++)
        #pragma unroll
        for (int hf = 0; hf < 2; hf++) {
            int row = wm*32 + mf*16 + g + hf*8;
            int grow = i0 + row;
            size_t base = ((size_t)b * NN + grow) * DR;
            #pragma unroll
            for (int nf = 0; nf < 4; nf++) {
                int col = wn*32 + nf*8 + 2*tig;
                float v0 = acc[mf][nf][hf*2 + 0] + bias[col];
                float v1 = acc[mf][nf][hf*2 + 1] + bias[col + 1];
                size_t idx = base + col;
                if (MODE == 0) {
                    v0 = tanhf(v0); v1 = tanhf(v1);
                    *(float2*)(dst + idx) = make_float2(v0, v1);
                } else if (MODE == 1) {
                    v0 = hsrc[idx] + v0 * DT_VAL;
                    v1 = hsrc[idx + 1] + v1 * DT_VAL;
                    *(float2*)(dst + idx) = make_float2(v0, v1);
                    if (writeHist) {
                        size_t hidx = (((size_t)b * TT + tIdx) * NN + grow) * DR + col;
                        *(__half2*)(g_hv1h + hidx) = __floats2half2_rn(v0, v1);
                    }
                } else if (MODE == 2) {
                    v0 = 1.f / (1.f + __expf(-v0));
                    v1 = 1.f / (1.f + __expf(-v1));
                    *(float2*)(dst + idx) = make_float2(v0, v1);
                } else {
                    float c0 = tanhf(v0), c1 = tanhf(v1);
                    float h0v = hsrc[idx], h1v = hsrc[idx + 1];
                    v0 = h0v + ob * zsrc[idx]     * (c0 - h0v);
                    v1 = h1v + ob * zsrc[idx + 1] * (c1 - h1v);
                    *(float2*)(dst + idx) = make_float2(v0, v1);
                }
            }
        }
}

// ---------------- the persistent kernel ----------------
__global__ __launch_bounds__(256) void persist_kernel(
    const float* __restrict__ values, const float* __restrict__ masks,
    const float* __restrict__ b0, const float* __restrict__ b1,
    const float* __restrict__ bout, const float* __restrict__ bz,
    const float* __restrict__ br, const float* __restrict__ bh)
{
    __shared__ __half smh[2 * 64 * AST + 2 * KC * BST];

    const int b  = blockIdx.x >> 4;
    const int i0 = (blockIdx.x & 15) * 64;

    const __half* tW0   = g_Wh + 0 * WSLOT;
    const __half* tW1   = g_Wh + 1 * WSLOT;
    const __half* tWout = g_Wh + 2 * WSLOT;
    const __half* tWz   = g_Wh + 3 * WSLOT;
    const __half* tWr   = g_Wh + 4 * WSLOT;
    const __half* tWh   = g_Wh + 5 * WSLOT;

    float* h   = g_h;
    float* u   = g_u;
    float* hv1 = g_hv1;
    float* z   = g_z;
    float* r   = g_r;

    __half* cur = g_Pb;
    __half* nxt = g_Pa;
    unsigned bar = 0;
    auto swap = [&]() { __half* t2 = cur; cur = nxt; nxt = t2; };

    // ---- initial ODE-only step: h <- h + ode(h)*dt ----
    dev_proj<false,false>(smh, b, i0, 0, nullptr, nullptr, h, nullptr,
                          tW0, nxt, 128, 0, 128);
    swap(); grid_barrier(++bar * GRIDN);
    dev_amult<0>(smh, b, i0, cur, 128, 0, b0, u, nullptr, nullptr, 0, false);
    dev_proj<false,false>(smh, b, i0, 0, nullptr, nullptr, u, nullptr,
                          tW1, nxt, 128, 0, 128);
    swap(); grid_barrier(++bar * GRIDN);
    dev_amult<0>(smh, b, i0, cur, 128, 0, b1, u, nullptr, nullptr, 0, false);
    dev_proj<false,false>(smh, b, i0, 0, nullptr, nullptr, u, nullptr,
                          tWout, nxt, 128, 0, 128);
    swap(); grid_barrier(++bar * GRIDN);
    dev_amult<1>(smh, b, i0, cur, 128, 0, bout, h, h, nullptr, 0, false);

    for (int t = 0; t < TT; t++) {
        // ODE stage 1
        dev_proj<false,false>(smh, b, i0, 0, nullptr, nullptr, h, nullptr,
                              tW0, nxt, 128, 0, 128);
        swap(); grid_barrier(++bar * GRIDN);
        dev_amult<0>(smh, b, i0, cur, 128, 0, b0, u, nullptr, nullptr, 0, false);
        // ODE stage 2
        dev_proj<false,false>(smh, b, i0, 0, nullptr, nullptr, u, nullptr,
                              tW1, nxt, 128, 0, 128);
        swap(); grid_barrier(++bar * GRIDN);
        dev_amult<0>(smh, b, i0, cur, 128, 0, b1, u, nullptr, nullptr, 0, false);
        // ODE stage 3 -> hv1 (+half history)
        dev_proj<false,false>(smh, b, i0, 0, nullptr, nullptr, u, nullptr,
                              tWout, nxt, 128, 0, 128);
        swap(); grid_barrier(++bar * GRIDN);
        dev_amult<1>(smh, b, i0, cur, 128, 0, bout, hv1, h, nullptr, t, true);
        // gate projections: [x*m | hv1] @ {Wz, Wr} -> nxt (ld 256)
        dev_proj<true,false>(smh, b, i0, t, values, masks, hv1, nullptr,
                             tWz, nxt, 256, 0, 192);
        dev_proj<true,false>(smh, b, i0, t, values, masks, hv1, nullptr,
                             tWr, nxt, 256, 128, 192);
        swap(); grid_barrier(++bar * GRIDN);
        // gate A-mults: z and r
        dev_amult<2>(smh, b, i0, cur, 256, 0,   bz, z, nullptr, nullptr, 0, false);
        dev_amult<2>(smh, b, i0, cur, 256, 128, br, r, nullptr, nullptr, 0, false);
        // candidate projection: [x*m | r*hv1] @ Wh -> nxt (ld 128)
        dev_proj<true,true>(smh, b, i0, t, values, masks, hv1, r,
                            tWh, nxt, 128, 0, 192);
        swap(); grid_barrier(++bar * GRIDN);
        // blend: h = hv1 + obs*z*(tanh(A@P + bh) - hv1)
        dev_amult<3>(smh, b, i0, cur, 128, 0, bh, h, hv1, z, t, false);
    }
}

// ---------------- batched output head ----------------
__global__ __launch_bounds__(128) void outgemm_h(
    const __half* __restrict__ hv1h, const __half* __restrict__ Wo,
    const float* __restrict__ bo, float* __restrict__ out)
{
    __shared__ __half As[64 * BST];
    __shared__ __half Ws[DR * 72];

    const int n0 = blockIdx.x * 64;
    const int t  = blockIdx.y + 1;
    const int b  = blockIdx.z;

    const int tid  = threadIdx.x;
    const int lane = tid & 31, warp = tid >> 5;
    const int wm = warp & 1, wn = warp >> 1;
    const int g  = lane >> 2, tig = lane & 3;
    const int quad = lane >> 3;
    const int lrow = (quad & 1) * 8 + (lane & 7);
    const int lcol = (quad >> 1) * 8;

    const __half* Hb = hv1h + (((size_t)b * TT + t) * NN + n0) * DR;

    for (int i = tid; i < 64 * 16; i += 128) {
        int r = i >> 4, cq = i & 15;
        *(uint4*)&As[r * BST + cq * 8] = *(const uint4*)(Hb + (size_t)r * DR + cq * 8);
    }
    for (int i = tid; i < DR * 8; i += 128) {
        int r = i >> 3, cq = i & 7;
        *(uint4*)&Ws[r * 72 + cq * 8] = *(const uint4*)(Wo + (size_t)r * DIN + cq * 8);
    }
    __syncthreads();

    const uint32_t sAs = (uint32_t)__cvta_generic_to_shared(As);
    const uint32_t sWs = (uint32_t)__cvta_generic_to_shared(Ws);

    float acc[2][4][4] = {};
    #pragma unroll
    for (int ks = 0; ks < 8; ks++) {
        const int kk = ks * 16;
        uint32_t a[2][4], bq[2][4];
        #pragma unroll
        for (int mf = 0; mf < 2; mf++)
            ldsm4(a[mf], sAs + ((wm*32 + mf*16 + lrow) * BST + kk + lcol) * 2);
        #pragma unroll
        for (int p = 0; p < 2; p++)
            ldsm4t(bq[p], sWs + ((kk + lrow) * 72 + wn*32 + p*16 + lcol) * 2);
        #pragma unroll
        for (int mf = 0; mf < 2; mf++) {
            MMA_F16(acc[mf][0], a[mf], &bq[0][0]);
            MMA_F16(acc[mf][1], a[mf], &bq[0][2]);
            MMA_F16(acc[mf][2], a[mf], &bq[1][0]);
            MMA_F16(acc[mf][3], a[mf], &bq[1][2]);
        }
    }

    float* obp = out + (((size_t)b * (TT - 1) + (t - 1)) * NN + n0) * DIN;
    #pragma unroll
    for (int mf = 0; mf < 2; mf++)
        #pragma unroll
        for (int hf = 0; hf < 2; hf++) {
            int row = wm*32 + mf*16 + g + hf*8;
            #pragma unroll
            for (int nf = 0; nf < 4; nf++) {
                int col = wn*32 + nf*8 + 2*tig;
                float v0 = acc[mf][nf][hf*2 + 0] + bo[col];
                float v1 = acc[mf][nf][hf*2 + 1] + bo[col + 1];
                *(float2*)(obp + (size_t)row * DIN + col) = make_float2(v0, v1);
            }
        }
}

// ---------------- driver ----------------
extern "C" void kernel_launch(void* const* d_in, const int* in_sizes, int n_in,
                              void* d_out, int out_size)
{
    const float* values = (const float*)d_in[0];
    const float* masks  = (const float*)d_in[1];
    const float* A      = (const float*)d_in[2];
    const float* h0     = (const float*)d_in[3];
    const float* W0   = (const float*)d_in[4];
    const float* b0   = (const float*)d_in[5];
    const float* W1   = (const float*)d_in[6];
    const float* b1   = (const float*)d_in[7];
    const float* Wout = (const float*)d_in[8];
    const float* bout = (const float*)d_in[9];
    const float* Wz   = (const float*)d_in[10];
    const float* bz   = (const float*)d_in[11];
    const float* Wr   = (const float*)d_in[12];
    const float* br   = (const float*)d_in[13];
    const float* Wh   = (const float*)d_in[14];
    const float* bh   = (const float*)d_in[15];
    const float* Wo   = (const float*)d_in[16];
    const float* bo   = (const float*)d_in[17];
    float* out = (float*)d_out;

    __half *Woh, *hv1h;
    cudaGetSymbolAddress((void**)&Woh,  g_Woh);
    cudaGetSymbolAddress((void**)&hv1h, g_hv1h);

    init_h_kernel<<<256, 256>>>(h0);
    round_A_kernel<<<512, 256>>>(A);
    round_W_kernel<<<128, 256>>>(W0, W1, Wout, Wz, Wr, Wh, Wo);
    obs_kernel<<<BB * TT, 256>>>(masks);

    persist_kernel<<<GRIDN, 256>>>(values, masks, b0, b1, bout, bz, br, bh);

    dim3 og(NN / 64, TT - 1, BB);
    outgemm_h<<<og, 128>>>(hv1h, Woh, bo, out);
}